// round 5
// baseline (speedup 1.0000x reference)
#include <cuda_runtime.h>
#include <cuda_bf16.h>
#include <math.h>

#define NN 50000
#define NE 800000
#define D  64
#define NG 128
#define DH 32
#define NC 6

// ---------------- scratch (device globals; no allocation allowed) ----------
__device__ float g_h[NN * D];        // hidden state
__device__ float g_aggH[NN * D];     // neighbor-sum of h (pre-GEMM, by linearity)
__device__ float g_pooled[NG * D];   // graph pooling sums
__device__ int   g_cnt[NG];          // nodes per graph
__device__ int   g_rowcnt[NN];       // per-dst edge counts
__device__ int   g_rowoff[NN + 1];   // CSR row offsets
__device__ int   g_cursor[NN];       // placement cursors
__device__ int   g_csrc[NE];         // CSR src indices (dst-sorted)
__device__ float g_Wc[2 * 192 * 64]; // Wc[l][r][k] = sum_j W[l][k][j]*w_ih[r][j]

__device__ __forceinline__ float sigf(float x) {
    return __fdividef(1.f, 1.f + __expf(-x));
}
__device__ __forceinline__ float tanhfast(float x) {
    return __fdividef(2.f, 1.f + __expf(-2.f * x)) - 1.f;
}

// bf16 split helpers: v = hi + lo with |residual| ~ 2^-16 |v|
__device__ __forceinline__ void split1(float v, __nv_bfloat16& h, __nv_bfloat16& l) {
    h = __float2bfloat16(v);
    l = __float2bfloat16(v - __bfloat162float(h));
}
__device__ __forceinline__ void split_pair(float v0, float v1, unsigned& hi, unsigned& lo) {
    __nv_bfloat16 h0, l0, h1, l1;
    split1(v0, h0, l0);
    split1(v1, h1, l1);
    hi = (unsigned)__bfloat16_as_ushort(h0) | ((unsigned)__bfloat16_as_ushort(h1) << 16);
    lo = (unsigned)__bfloat16_as_ushort(l0) | ((unsigned)__bfloat16_as_ushort(l1) << 16);
}

// mma.sync m16n8k16 bf16 -> f32 accumulate
__device__ __forceinline__ void mma16816(float* c, const unsigned* a, const unsigned* b) {
    asm volatile(
        "mma.sync.aligned.m16n8k16.row.col.f32.bf16.bf16.f32 "
        "{%0,%1,%2,%3}, {%4,%5,%6,%7}, {%8,%9}, {%0,%1,%2,%3};"
        : "+f"(c[0]), "+f"(c[1]), "+f"(c[2]), "+f"(c[3])
        : "r"(a[0]), "r"(a[1]), "r"(a[2]), "r"(a[3]), "r"(b[0]), "r"(b[1]));
}

// ---------------- zero counters ----------------------------------------------
__global__ void k_zero() {
    int i = blockIdx.x * 256 + threadIdx.x;
    if (i < NN) g_rowcnt[i] = 0;
    if (i < NG * D) g_pooled[i] = 0.f;
    if (i < NG) g_cnt[i] = 0;
}

// ---------------- histogram dst degrees + per-graph node counts --------------
__global__ void k_hist(const int* __restrict__ ei, const int* __restrict__ batch) {
    int t = blockIdx.x * 256 + threadIdx.x;
    if (t < NE) atomicAdd(&g_rowcnt[ei[NE + t]], 1);
    if (t < NN) atomicAdd(&g_cnt[batch[t]], 1);
}

// ---------------- single-block exclusive scan of row counts ------------------
__global__ void k_scan() {
    __shared__ int part[1024];
    const int CH = (NN + 1023) / 1024;  // 49
    int t = threadIdx.x;
    int base = t * CH;
    int sum = 0;
    for (int i = 0; i < CH; i++) {
        int idx = base + i;
        if (idx < NN) sum += g_rowcnt[idx];
    }
    part[t] = sum;
    __syncthreads();
    for (int off = 1; off < 1024; off <<= 1) {
        int v = (t >= off) ? part[t - off] : 0;
        __syncthreads();
        part[t] += v;
        __syncthreads();
    }
    int run = t ? part[t - 1] : 0;
    for (int i = 0; i < CH; i++) {
        int idx = base + i;
        if (idx < NN) {
            int c = g_rowcnt[idx];
            g_rowoff[idx] = run;
            g_cursor[idx] = run;
            run += c;
        }
    }
    if (t == 1023) g_rowoff[NN] = NE;
}

// ---------------- CSR placement ----------------------------------------------
__global__ void k_place(const int* __restrict__ ei) {
    int e = blockIdx.x * 256 + threadIdx.x;
    if (e < NE) {
        int dst = ei[NE + e];
        int pos = atomicAdd(&g_cursor[dst], 1);
        g_csrc[pos] = ei[e];
    }
}

// ---------------- Wc[l] = W[l] @ w_ih^T  (stored in w_ih row layout) ---------
__global__ void k_prep(const float* __restrict__ W, const float* __restrict__ w_ih) {
    int l = blockIdx.x;
    const float* Wl = W + l * 64 * 64;
    for (int idx = threadIdx.x; idx < 192 * 64; idx += 256) {
        int r = idx >> 6, k = idx & 63;
        float s = 0.f;
#pragma unroll 16
        for (int j = 0; j < 64; j++) s += Wl[k * 64 + j] * w_ih[r * 64 + j];
        g_Wc[l * 192 * 64 + r * 64 + k] = s;
    }
}

// ---------------- CSR gather: aggH[n] = sum_{e in adj(n)} h[src[e]] ----------
// 16 threads per node, one float4 quad each; 4-way unrolled for MLP.
__global__ void k_gather(const float* __restrict__ x, int layer) {
    const float* hin = layer ? g_h : x;
    int t = blockIdx.x * 256 + threadIdx.x;
    if (t >= NN * 16) return;
    int node = t >> 4;
    int q = t & 15;

    int s = g_rowoff[node];
    int e_ = g_rowoff[node + 1];

    float4 acc = make_float4(0.f, 0.f, 0.f, 0.f);
    int e = s;
    for (; e + 4 <= e_; e += 4) {
        int s0 = g_csrc[e], s1 = g_csrc[e + 1], s2 = g_csrc[e + 2], s3 = g_csrc[e + 3];
        float4 v0 = *(const float4*)&hin[s0 * 64 + q * 4];
        float4 v1 = *(const float4*)&hin[s1 * 64 + q * 4];
        float4 v2 = *(const float4*)&hin[s2 * 64 + q * 4];
        float4 v3 = *(const float4*)&hin[s3 * 64 + q * 4];
        acc.x += v0.x + v1.x + v2.x + v3.x;
        acc.y += v0.y + v1.y + v2.y + v3.y;
        acc.z += v0.z + v1.z + v2.z + v3.z;
        acc.w += v0.w + v1.w + v2.w + v3.w;
    }
    for (; e < e_; e++) {
        int src = g_csrc[e];
        float4 v = *(const float4*)&hin[src * 64 + q * 4];
        acc.x += v.x; acc.y += v.y; acc.z += v.z; acc.w += v.w;
    }
    *(float4*)&g_aggH[node * 64 + q * 4] = acc;
}

// ---------------- fused GRU gates via bf16x3 tensor cores -------------------
// gi uses aggH with combined weight Wc[l] (= W[l] @ w_ih^T), gh uses h with
// w_hh. Warp w owns d-slice [8w, 8w+8) of ALL six gate blocks.
__global__ __launch_bounds__(256, 1)
void k_gates(const float* __restrict__ x,
             const float* __restrict__ w_hh,
             const float* __restrict__ b_ih, const float* __restrict__ b_hh,
             const int* __restrict__ batch, int layer) {
    __shared__ __align__(16) __nv_bfloat16 s_ahi[16 * 72];
    __shared__ __align__(16) __nv_bfloat16 s_alo[16 * 72];
    __shared__ __align__(16) __nv_bfloat16 s_hhi[16 * 72];
    __shared__ __align__(16) __nv_bfloat16 s_hlo[16 * 72];
    __shared__ __align__(16) float s_hf[16 * 66];

    int tid = threadIdx.x;
    int wid = tid >> 5, lane = tid & 31;
    int tg = lane & 3, gid = lane >> 2;
    int dbase = wid * 8;
    int d0 = dbase + tg * 2;

    // B fragments: gates 0..2 = Wc[l] rows (combined), 3..5 = w_hh rows.
    unsigned Bhi[6][4][2], Blo[6][4][2];
#pragma unroll
    for (int g = 0; g < 6; g++) {
        const float* wm = (g < 3) ? (g_Wc + layer * 192 * 64) : w_hh;
        const float* wr = wm + ((g % 3) * 64 + dbase + gid) * 64;
#pragma unroll
        for (int kt = 0; kt < 4; kt++) {
            int k0 = kt * 16 + tg * 2;
            split_pair(wr[k0],     wr[k0 + 1], Bhi[g][kt][0], Blo[g][kt][0]);
            split_pair(wr[k0 + 8], wr[k0 + 9], Bhi[g][kt][1], Blo[g][kt][1]);
        }
    }
    float bi0[2], bi1[2], bi2[2], bh0[2], bh1[2], bh2[2];
#pragma unroll
    for (int j = 0; j < 2; j++) {
        bi0[j] = b_ih[d0 + j];       bh0[j] = b_hh[d0 + j];
        bi1[j] = b_ih[64 + d0 + j];  bh1[j] = b_hh[64 + d0 + j];
        bi2[j] = b_ih[128 + d0 + j]; bh2[j] = b_hh[128 + d0 + j];
    }

    const float* hin = layer ? g_h : x;

    for (int chunk = blockIdx.x * 16; chunk < NN; chunk += gridDim.x * 16) {
        __syncthreads();
#pragma unroll
        for (int i = 0; i < 4; i++) {
            int idx = tid + i * 256;
            int row = idx >> 6, col = idx & 63;
            float a = g_aggH[chunk * 64 + idx];
            float h = hin[chunk * 64 + idx];
            __nv_bfloat16 hh, ll;
            split1(a, hh, ll);
            s_ahi[row * 72 + col] = hh;
            s_alo[row * 72 + col] = ll;
            split1(h, hh, ll);
            s_hhi[row * 72 + col] = hh;
            s_hlo[row * 72 + col] = ll;
            s_hf[row * 66 + col] = h;
        }
        __syncthreads();

        float C[6][4];
#pragma unroll
        for (int g = 0; g < 6; g++)
#pragma unroll
            for (int q = 0; q < 4; q++) C[g][q] = 0.f;

#pragma unroll
        for (int kt = 0; kt < 4; kt++) {
            int k0 = kt * 16 + tg * 2;
            unsigned ahi[4], alo[4];
            // aggH tile -> gates 0..2 (combined-weight i_r, i_z, i_n)
            ahi[0] = *(const unsigned*)&s_ahi[(gid)     * 72 + k0];
            ahi[1] = *(const unsigned*)&s_ahi[(gid + 8) * 72 + k0];
            ahi[2] = *(const unsigned*)&s_ahi[(gid)     * 72 + k0 + 8];
            ahi[3] = *(const unsigned*)&s_ahi[(gid + 8) * 72 + k0 + 8];
            alo[0] = *(const unsigned*)&s_alo[(gid)     * 72 + k0];
            alo[1] = *(const unsigned*)&s_alo[(gid + 8) * 72 + k0];
            alo[2] = *(const unsigned*)&s_alo[(gid)     * 72 + k0 + 8];
            alo[3] = *(const unsigned*)&s_alo[(gid + 8) * 72 + k0 + 8];
#pragma unroll
            for (int g = 0; g < 3; g++) {
                mma16816(C[g], ahi, Bhi[g][kt]);
                mma16816(C[g], ahi, Blo[g][kt]);
                mma16816(C[g], alo, Bhi[g][kt]);
            }
            // h tile -> gates 3..5 (h_r, h_z, h_n)
            ahi[0] = *(const unsigned*)&s_hhi[(gid)     * 72 + k0];
            ahi[1] = *(const unsigned*)&s_hhi[(gid + 8) * 72 + k0];
            ahi[2] = *(const unsigned*)&s_hhi[(gid)     * 72 + k0 + 8];
            ahi[3] = *(const unsigned*)&s_hhi[(gid + 8) * 72 + k0 + 8];
            alo[0] = *(const unsigned*)&s_hlo[(gid)     * 72 + k0];
            alo[1] = *(const unsigned*)&s_hlo[(gid + 8) * 72 + k0];
            alo[2] = *(const unsigned*)&s_hlo[(gid)     * 72 + k0 + 8];
            alo[3] = *(const unsigned*)&s_hlo[(gid + 8) * 72 + k0 + 8];
#pragma unroll
            for (int g = 3; g < 6; g++) {
                mma16816(C[g], ahi, Bhi[g][kt]);
                mma16816(C[g], ahi, Blo[g][kt]);
                mma16816(C[g], alo, Bhi[g][kt]);
            }
        }

        // GRU elementwise epilogue (per-thread: 2 rows x 2 dims)
#pragma unroll
        for (int p = 0; p < 2; p++) {
            int row = gid + p * 8;
            int node = chunk + row;
#pragma unroll
            for (int j = 0; j < 2; j++) {
                int q = p * 2 + j;
                float r  = sigf(C[0][q] + bi0[j] + C[3][q] + bh0[j]);
                float z  = sigf(C[1][q] + bi1[j] + C[4][q] + bh1[j]);
                float nn = tanhfast(C[2][q] + bi2[j] + r * (C[5][q] + bh2[j]));
                float ho = s_hf[row * 66 + d0 + j];
                float hv = (1.f - z) * nn + z * ho;
                if (layer == 0) {
                    g_h[node * 64 + d0 + j] = hv;
                } else {
                    atomicAdd(&g_pooled[batch[node] * 64 + d0 + j], fmaxf(hv, 0.f));
                }
            }
        }
    }
}

// ---------------- mean pool + fc1(relu) + fc2 + log_softmax -----------------
__global__ void k_poolfc(const float* __restrict__ fc1w, const float* __restrict__ fc1b,
                         const float* __restrict__ fc2w, const float* __restrict__ fc2b,
                         float* __restrict__ out) {
    int g = threadIdx.x;
    if (g >= NG) return;
    float inv = 1.f / fmaxf((float)g_cnt[g], 1.f);
    float p[D];
#pragma unroll
    for (int k = 0; k < D; k++) p[k] = g_pooled[g * D + k] * inv;

    float y[DH];
#pragma unroll
    for (int j = 0; j < DH; j++) {
        float s = fc1b[j];
#pragma unroll
        for (int k = 0; k < D; k++) s += p[k] * fc1w[j * D + k];
        y[j] = fmaxf(s, 0.f);
    }

    float z[NC];
    float mx = -1e30f;
#pragma unroll
    for (int c = 0; c < NC; c++) {
        float s = fc2b[c];
#pragma unroll
        for (int j = 0; j < DH; j++) s += y[j] * fc2w[c * DH + j];
        z[c] = s;
        mx = fmaxf(mx, s);
    }
    float lse = 0.f;
#pragma unroll
    for (int c = 0; c < NC; c++) lse += expf(z[c] - mx);
    lse = logf(lse) + mx;
#pragma unroll
    for (int c = 0; c < NC; c++) out[g * NC + c] = z[c] - lse;
}

// ---------------- launch -----------------------------------------------------
extern "C" void kernel_launch(void* const* d_in, const int* in_sizes, int n_in,
                              void* d_out, int out_size) {
    const float* x     = (const float*)d_in[0];
    const int*   ei    = (const int*)d_in[1];
    const int*   batch = (const int*)d_in[2];
    const float* W     = (const float*)d_in[3];
    const float* w_ih  = (const float*)d_in[4];
    const float* w_hh  = (const float*)d_in[5];
    const float* b_ih  = (const float*)d_in[6];
    const float* b_hh  = (const float*)d_in[7];
    const float* fc1w  = (const float*)d_in[8];
    const float* fc1b  = (const float*)d_in[9];
    const float* fc2w  = (const float*)d_in[10];
    const float* fc2b  = (const float*)d_in[11];
    float* out = (float*)d_out;

    k_zero<<<(NN + 255) / 256, 256>>>();
    k_hist<<<(NE + 255) / 256, 256>>>(ei, batch);
    k_scan<<<1, 1024>>>();
    k_place<<<(NE + 255) / 256, 256>>>(ei);
    k_prep<<<2, 256>>>(W, w_ih);

    for (int l = 0; l < 2; l++) {
        k_gather<<<(NN * 16 + 255) / 256, 256>>>(x, l);
        k_gates<<<296, 256>>>(x, w_hh, b_ih, b_hh, batch, l);
    }
    k_poolfc<<<1, 128>>>(fc1w, fc1b, fc2w, fc2b, out);
}

// round 6
// speedup vs baseline: 1.0556x; 1.0556x over previous
#include <cuda_runtime.h>
#include <cuda_bf16.h>
#include <math.h>

#define NN 50000
#define NE 800000
#define D  64
#define NG 128
#define DH 32
#define NC 6

// ---------------- scratch (device globals; no allocation allowed) ----------
__device__ float g_h[NN * D];         // hidden state after layer 0
__device__ float g_agg0[NN * D];      // neighbor-sum of h, layer 0
__device__ float g_agg1[NN * D];      // neighbor-sum of h, layer 1
__device__ float g_pooled[NG * D];    // graph pooling sums
__device__ int   g_cnt[NG];           // nodes per graph
__device__ float g_Wc[2 * 192 * 64];  // Wc[l][r][k] = sum_j W[l][k][j]*w_ih[r][j]

__device__ __forceinline__ float sigf(float x) {
    return __fdividef(1.f, 1.f + __expf(-x));
}
__device__ __forceinline__ float tanhfast(float x) {
    return __fdividef(2.f, 1.f + __expf(-2.f * x)) - 1.f;
}

// bf16 split helpers: v = hi + lo with |residual| ~ 2^-16 |v|
__device__ __forceinline__ void split1(float v, __nv_bfloat16& h, __nv_bfloat16& l) {
    h = __float2bfloat16(v);
    l = __float2bfloat16(v - __bfloat162float(h));
}
__device__ __forceinline__ void split_pair(float v0, float v1, unsigned& hi, unsigned& lo) {
    __nv_bfloat16 h0, l0, h1, l1;
    split1(v0, h0, l0);
    split1(v1, h1, l1);
    hi = (unsigned)__bfloat16_as_ushort(h0) | ((unsigned)__bfloat16_as_ushort(h1) << 16);
    lo = (unsigned)__bfloat16_as_ushort(l0) | ((unsigned)__bfloat16_as_ushort(l1) << 16);
}

// mma.sync m16n8k16 bf16 -> f32 accumulate
__device__ __forceinline__ void mma16816(float* c, const unsigned* a, const unsigned* b) {
    asm volatile(
        "mma.sync.aligned.m16n8k16.row.col.f32.bf16.bf16.f32 "
        "{%0,%1,%2,%3}, {%4,%5,%6,%7}, {%8,%9}, {%0,%1,%2,%3};"
        : "+f"(c[0]), "+f"(c[1]), "+f"(c[2]), "+f"(c[3])
        : "r"(a[0]), "r"(a[1]), "r"(a[2]), "r"(a[3]), "r"(b[0]), "r"(b[1]));
}

// ---------------- init: zero both agg buffers + pooled + counts ------------
__global__ void k_init() {
    int i = blockIdx.x * 256 + threadIdx.x;
    if (i < NN * D / 4) {
        ((float4*)g_agg0)[i] = make_float4(0.f, 0.f, 0.f, 0.f);
        ((float4*)g_agg1)[i] = make_float4(0.f, 0.f, 0.f, 0.f);
    }
    if (i < NG * D) g_pooled[i] = 0.f;
    if (i < NG) g_cnt[i] = 0;
}

// ---------------- per-graph node counts -------------------------------------
__global__ void k_count(const int* __restrict__ batch) {
    int n = blockIdx.x * 256 + threadIdx.x;
    if (n < NN) atomicAdd(&g_cnt[batch[n]], 1);
}

// ---------------- Wc[l] = W[l] @ w_ih^T  (stored in w_ih row layout) ---------
__global__ void k_prep(const float* __restrict__ W, const float* __restrict__ w_ih) {
    int l = blockIdx.x;
    const float* Wl = W + l * 64 * 64;
    for (int idx = threadIdx.x; idx < 192 * 64; idx += 256) {
        int r = idx >> 6, k = idx & 63;
        float s = 0.f;
#pragma unroll 16
        for (int j = 0; j < 64; j++) s += Wl[k * 64 + j] * w_ih[r * 64 + j];
        g_Wc[l * 192 * 64 + r * 64 + k] = s;
    }
}

// ---------------- edge scatter: agg[dst] += h[src] --------------------------
// One thread per (edge, 16B quad): float4 gather from L2-resident h,
// 128-bit vector atomic into agg (sm_90+ atomicAdd(float4*)).
__global__ void k_scatter(const int* __restrict__ ei, const float* __restrict__ x,
                          int layer) {
    const float* hin = layer ? g_h : x;
    float* agg = layer ? g_agg1 : g_agg0;
    int t = blockIdx.x * 256 + threadIdx.x;
    if (t >= NE * 16) return;
    int e = t >> 4;
    int q = t & 15;
    int src = ei[e];
    int dst = ei[NE + e];
    float4 v = *reinterpret_cast<const float4*>(&hin[src * 64 + q * 4]);
    atomicAdd(reinterpret_cast<float4*>(&agg[dst * 64 + q * 4]), v);
}

// ---------------- fused GRU gates via bf16x3 tensor cores -------------------
// gi uses aggH (raw neighbor sum) with combined weight Wc[l] = W[l] @ w_ih^T,
// gh uses h with w_hh. Warp w owns d-slice [8w, 8w+8) of ALL six gate blocks
// -> full GRU elementwise epilogue stays in C-fragment registers.
__global__ __launch_bounds__(256, 1)
void k_gates(const float* __restrict__ x,
             const float* __restrict__ w_hh,
             const float* __restrict__ b_ih, const float* __restrict__ b_hh,
             const int* __restrict__ batch, int layer) {
    __shared__ __align__(16) __nv_bfloat16 s_ahi[16 * 72];
    __shared__ __align__(16) __nv_bfloat16 s_alo[16 * 72];
    __shared__ __align__(16) __nv_bfloat16 s_hhi[16 * 72];
    __shared__ __align__(16) __nv_bfloat16 s_hlo[16 * 72];
    __shared__ __align__(16) float s_hf[16 * 66];

    int tid = threadIdx.x;
    int wid = tid >> 5, lane = tid & 31;
    int tg = lane & 3, gid = lane >> 2;
    int dbase = wid * 8;
    int d0 = dbase + tg * 2;

    // B fragments: gates 0..2 = Wc[l] rows (combined), 3..5 = w_hh rows.
    unsigned Bhi[6][4][2], Blo[6][4][2];
#pragma unroll
    for (int g = 0; g < 6; g++) {
        const float* wm = (g < 3) ? (g_Wc + layer * 192 * 64) : w_hh;
        const float* wr = wm + ((g % 3) * 64 + dbase + gid) * 64;
#pragma unroll
        for (int kt = 0; kt < 4; kt++) {
            int k0 = kt * 16 + tg * 2;
            split_pair(wr[k0],     wr[k0 + 1], Bhi[g][kt][0], Blo[g][kt][0]);
            split_pair(wr[k0 + 8], wr[k0 + 9], Bhi[g][kt][1], Blo[g][kt][1]);
        }
    }
    float bi0[2], bi1[2], bi2[2], bh0[2], bh1[2], bh2[2];
#pragma unroll
    for (int j = 0; j < 2; j++) {
        bi0[j] = b_ih[d0 + j];       bh0[j] = b_hh[d0 + j];
        bi1[j] = b_ih[64 + d0 + j];  bh1[j] = b_hh[64 + d0 + j];
        bi2[j] = b_ih[128 + d0 + j]; bh2[j] = b_hh[128 + d0 + j];
    }

    const float* hin = layer ? g_h : x;
    const float* agg = layer ? g_agg1 : g_agg0;

    for (int chunk = blockIdx.x * 16; chunk < NN; chunk += gridDim.x * 16) {
        __syncthreads();
#pragma unroll
        for (int i = 0; i < 4; i++) {
            int idx = tid + i * 256;
            int row = idx >> 6, col = idx & 63;
            float a = agg[chunk * 64 + idx];
            float h = hin[chunk * 64 + idx];
            __nv_bfloat16 hh, ll;
            split1(a, hh, ll);
            s_ahi[row * 72 + col] = hh;
            s_alo[row * 72 + col] = ll;
            split1(h, hh, ll);
            s_hhi[row * 72 + col] = hh;
            s_hlo[row * 72 + col] = ll;
            s_hf[row * 66 + col] = h;
        }
        __syncthreads();

        float C[6][4];
#pragma unroll
        for (int g = 0; g < 6; g++)
#pragma unroll
            for (int q = 0; q < 4; q++) C[g][q] = 0.f;

#pragma unroll
        for (int kt = 0; kt < 4; kt++) {
            int k0 = kt * 16 + tg * 2;
            unsigned ahi[4], alo[4];
            // aggH tile -> gates 0..2 (combined-weight i_r, i_z, i_n)
            ahi[0] = *(const unsigned*)&s_ahi[(gid)     * 72 + k0];
            ahi[1] = *(const unsigned*)&s_ahi[(gid + 8) * 72 + k0];
            ahi[2] = *(const unsigned*)&s_ahi[(gid)     * 72 + k0 + 8];
            ahi[3] = *(const unsigned*)&s_ahi[(gid + 8) * 72 + k0 + 8];
            alo[0] = *(const unsigned*)&s_alo[(gid)     * 72 + k0];
            alo[1] = *(const unsigned*)&s_alo[(gid + 8) * 72 + k0];
            alo[2] = *(const unsigned*)&s_alo[(gid)     * 72 + k0 + 8];
            alo[3] = *(const unsigned*)&s_alo[(gid + 8) * 72 + k0 + 8];
#pragma unroll
            for (int g = 0; g < 3; g++) {
                mma16816(C[g], ahi, Bhi[g][kt]);
                mma16816(C[g], ahi, Blo[g][kt]);
                mma16816(C[g], alo, Bhi[g][kt]);
            }
            // h tile -> gates 3..5 (h_r, h_z, h_n)
            ahi[0] = *(const unsigned*)&s_hhi[(gid)     * 72 + k0];
            ahi[1] = *(const unsigned*)&s_hhi[(gid + 8) * 72 + k0];
            ahi[2] = *(const unsigned*)&s_hhi[(gid)     * 72 + k0 + 8];
            ahi[3] = *(const unsigned*)&s_hhi[(gid + 8) * 72 + k0 + 8];
            alo[0] = *(const unsigned*)&s_hlo[(gid)     * 72 + k0];
            alo[1] = *(const unsigned*)&s_hlo[(gid + 8) * 72 + k0];
            alo[2] = *(const unsigned*)&s_hlo[(gid)     * 72 + k0 + 8];
            alo[3] = *(const unsigned*)&s_hlo[(gid + 8) * 72 + k0 + 8];
#pragma unroll
            for (int g = 3; g < 6; g++) {
                mma16816(C[g], ahi, Bhi[g][kt]);
                mma16816(C[g], ahi, Blo[g][kt]);
                mma16816(C[g], alo, Bhi[g][kt]);
            }
        }

        // GRU elementwise epilogue (per-thread: 2 rows x 2 dims)
#pragma unroll
        for (int p = 0; p < 2; p++) {
            int row = gid + p * 8;
            int node = chunk + row;
#pragma unroll
            for (int j = 0; j < 2; j++) {
                int q = p * 2 + j;
                float r  = sigf(C[0][q] + bi0[j] + C[3][q] + bh0[j]);
                float z  = sigf(C[1][q] + bi1[j] + C[4][q] + bh1[j]);
                float nn = tanhfast(C[2][q] + bi2[j] + r * (C[5][q] + bh2[j]));
                float ho = s_hf[row * 66 + d0 + j];
                float hv = (1.f - z) * nn + z * ho;
                if (layer == 0) {
                    g_h[node * 64 + d0 + j] = hv;
                } else {
                    atomicAdd(&g_pooled[batch[node] * 64 + d0 + j], fmaxf(hv, 0.f));
                }
            }
        }
    }
}

// ---------------- mean pool + fc1(relu) + fc2 + log_softmax -----------------
__global__ void k_poolfc(const float* __restrict__ fc1w, const float* __restrict__ fc1b,
                         const float* __restrict__ fc2w, const float* __restrict__ fc2b,
                         float* __restrict__ out) {
    int g = threadIdx.x;
    if (g >= NG) return;
    float inv = 1.f / fmaxf((float)g_cnt[g], 1.f);
    float p[D];
#pragma unroll
    for (int k = 0; k < D; k++) p[k] = g_pooled[g * D + k] * inv;

    float y[DH];
#pragma unroll
    for (int j = 0; j < DH; j++) {
        float s = fc1b[j];
#pragma unroll
        for (int k = 0; k < D; k++) s += p[k] * fc1w[j * D + k];
        y[j] = fmaxf(s, 0.f);
    }

    float z[NC];
    float mx = -1e30f;
#pragma unroll
    for (int c = 0; c < NC; c++) {
        float s = fc2b[c];
#pragma unroll
        for (int j = 0; j < DH; j++) s += y[j] * fc2w[c * DH + j];
        z[c] = s;
        mx = fmaxf(mx, s);
    }
    float lse = 0.f;
#pragma unroll
    for (int c = 0; c < NC; c++) lse += expf(z[c] - mx);
    lse = logf(lse) + mx;
#pragma unroll
    for (int c = 0; c < NC; c++) out[g * NC + c] = z[c] - lse;
}

// ---------------- launch -----------------------------------------------------
extern "C" void kernel_launch(void* const* d_in, const int* in_sizes, int n_in,
                              void* d_out, int out_size) {
    const float* x     = (const float*)d_in[0];
    const int*   ei    = (const int*)d_in[1];
    const int*   batch = (const int*)d_in[2];
    const float* W     = (const float*)d_in[3];
    const float* w_ih  = (const float*)d_in[4];
    const float* w_hh  = (const float*)d_in[5];
    const float* b_ih  = (const float*)d_in[6];
    const float* b_hh  = (const float*)d_in[7];
    const float* fc1w  = (const float*)d_in[8];
    const float* fc1b  = (const float*)d_in[9];
    const float* fc2w  = (const float*)d_in[10];
    const float* fc2b  = (const float*)d_in[11];
    float* out = (float*)d_out;

    k_init<<<(NN * D / 4 + 255) / 256, 256>>>();
    k_count<<<(NN + 255) / 256, 256>>>(batch);
    k_prep<<<2, 256>>>(W, w_ih);

    for (int l = 0; l < 2; l++) {
        k_scatter<<<(NE * 16) / 256, 256>>>(ei, x, l);
        k_gates<<<296, 256>>>(x, w_hh, b_ih, b_hh, batch, l);
    }
    k_poolfc<<<1, 128>>>(fc1w, fc1b, fc2w, fc2b, out);
}

// round 7
// speedup vs baseline: 2.8127x; 2.6646x over previous
#include <cuda_runtime.h>
#include <cuda_bf16.h>
#include <math.h>

#define NN 50000
#define NE 800000
#define D  64
#define NG 128
#define DH 32
#define NC 6

// ---------------- scratch (device globals; no allocation allowed) ----------
__device__ float g_h[NN * D];       // hidden state
__device__ float g_m[NN * D];       // per-node messages m = h @ W[l]
__device__ float g_agg[NN * D];     // scatter-add destination
__device__ float g_pooled[NG * D];  // graph pooling sums
__device__ int   g_cnt[NG];         // nodes per graph

__device__ __forceinline__ float sigf(float x) {
    return __fdividef(1.f, 1.f + __expf(-x));
}
__device__ __forceinline__ float tanhfast(float x) {
    return __fdividef(2.f, 1.f + __expf(-2.f * x)) - 1.f;
}

// bf16 split helpers: v = hi + lo with |residual| ~ 2^-16 |v|
__device__ __forceinline__ void split1(float v, __nv_bfloat16& h, __nv_bfloat16& l) {
    h = __float2bfloat16(v);
    l = __float2bfloat16(v - __bfloat162float(h));
}
__device__ __forceinline__ void split_pair(float v0, float v1, unsigned& hi, unsigned& lo) {
    __nv_bfloat16 h0, l0, h1, l1;
    split1(v0, h0, l0);
    split1(v1, h1, l1);
    hi = (unsigned)__bfloat16_as_ushort(h0) | ((unsigned)__bfloat16_as_ushort(h1) << 16);
    lo = (unsigned)__bfloat16_as_ushort(l0) | ((unsigned)__bfloat16_as_ushort(l1) << 16);
}

// mma.sync m16n8k16 bf16 -> f32 accumulate
__device__ __forceinline__ void mma16816(float* c, const unsigned* a, const unsigned* b) {
    asm volatile(
        "mma.sync.aligned.m16n8k16.row.col.f32.bf16.bf16.f32 "
        "{%0,%1,%2,%3}, {%4,%5,%6,%7}, {%8,%9}, {%0,%1,%2,%3};"
        : "+f"(c[0]), "+f"(c[1]), "+f"(c[2]), "+f"(c[3])
        : "r"(a[0]), "r"(a[1]), "r"(a[2]), "r"(a[3]), "r"(b[0]), "r"(b[1]));
}

// ---------------- init: zero pooled + counts, count nodes per graph ---------
__global__ void k_init(const int* __restrict__ batch) {
    int n = blockIdx.x * 256 + threadIdx.x;
    if (blockIdx.x == 0) {
        for (int i = threadIdx.x; i < NG * D; i += 256) g_pooled[i] = 0.f;
        if (threadIdx.x < NG) g_cnt[threadIdx.x] = 0;
    }
}
__global__ void k_count(const int* __restrict__ batch) {
    int n = blockIdx.x * 256 + threadIdx.x;
    if (n < NN) atomicAdd(&g_cnt[batch[n]], 1);
}

// ---------------- m = h @ W[layer] via bf16x3 tensor cores; zeroes agg ------
// 8 warps, warp w owns output dims [8w, 8w+8). 16-node M-tiles.
__global__ __launch_bounds__(256, 1)
void k_mgemm(const float* __restrict__ x, const float* __restrict__ W, int layer) {
    __shared__ __align__(16) __nv_bfloat16 s_hhi[16 * 72];
    __shared__ __align__(16) __nv_bfloat16 s_hlo[16 * 72];

    int tid = threadIdx.x;
    int wid = tid >> 5, lane = tid & 31;
    int tg = lane & 3, gid = lane >> 2;
    int dbase = wid * 8;
    int d0 = dbase + tg * 2;

    const float* Wl = W + layer * 64 * 64;
    // B[k][n] = Wl[k*64 + (dbase + gid)]
    unsigned Bhi[4][2], Blo[4][2];
#pragma unroll
    for (int kt = 0; kt < 4; kt++) {
        int k0 = kt * 16 + tg * 2;
        int nc = dbase + gid;
        split_pair(Wl[(k0)     * 64 + nc], Wl[(k0 + 1) * 64 + nc], Bhi[kt][0], Blo[kt][0]);
        split_pair(Wl[(k0 + 8) * 64 + nc], Wl[(k0 + 9) * 64 + nc], Bhi[kt][1], Blo[kt][1]);
    }

    const float* hin = layer ? g_h : x;

    for (int chunk = blockIdx.x * 16; chunk < NN; chunk += gridDim.x * 16) {
        __syncthreads();
#pragma unroll
        for (int i = 0; i < 4; i++) {
            int idx = tid + i * 256;
            int row = idx >> 6, col = idx & 63;
            float h = hin[chunk * 64 + idx];
            __nv_bfloat16 hh, ll;
            split1(h, hh, ll);
            s_hhi[row * 72 + col] = hh;
            s_hlo[row * 72 + col] = ll;
        }
        __syncthreads();

        float C[4] = {0.f, 0.f, 0.f, 0.f};
#pragma unroll
        for (int kt = 0; kt < 4; kt++) {
            int k0 = kt * 16 + tg * 2;
            unsigned ahi[4], alo[4];
            ahi[0] = *(const unsigned*)&s_hhi[(gid)     * 72 + k0];
            ahi[1] = *(const unsigned*)&s_hhi[(gid + 8) * 72 + k0];
            ahi[2] = *(const unsigned*)&s_hhi[(gid)     * 72 + k0 + 8];
            ahi[3] = *(const unsigned*)&s_hhi[(gid + 8) * 72 + k0 + 8];
            alo[0] = *(const unsigned*)&s_hlo[(gid)     * 72 + k0];
            alo[1] = *(const unsigned*)&s_hlo[(gid + 8) * 72 + k0];
            alo[2] = *(const unsigned*)&s_hlo[(gid)     * 72 + k0 + 8];
            alo[3] = *(const unsigned*)&s_hlo[(gid + 8) * 72 + k0 + 8];
            mma16816(C, ahi, Bhi[kt]);
            mma16816(C, ahi, Blo[kt]);
            mma16816(C, alo, Bhi[kt]);
        }

#pragma unroll
        for (int p = 0; p < 2; p++) {
            int node = chunk + gid + p * 8;
            float2 mv = make_float2(C[p * 2], C[p * 2 + 1]);
            *(float2*)&g_m[node * 64 + d0] = mv;
            *(float2*)&g_agg[node * 64 + d0] = make_float2(0.f, 0.f);
        }
    }
}

// ---------------- edge scatter: agg[dst] += m[src] --------------------------
__global__ void k_scatter(const int* __restrict__ ei) {
    int t = blockIdx.x * 256 + threadIdx.x;
    if (t >= NE * 16) return;
    int e = t >> 4;
    int q = t & 15;
    int src = ei[e];
    int dst = ei[NE + e];
    float4 v = *reinterpret_cast<const float4*>(&g_m[src * 64 + q * 4]);
    atomicAdd(reinterpret_cast<float4*>(&g_agg[dst * 64 + q * 4]), v);
}

// ---------------- fused GRU gates via bf16x3 tensor cores -------------------
// Warp w owns d-slice [8w, 8w+8) of ALL six gate blocks -> full GRU
// elementwise epilogue stays in C-fragment registers.
__global__ __launch_bounds__(256, 1)
void k_gates(const float* __restrict__ x,
             const float* __restrict__ w_ih, const float* __restrict__ w_hh,
             const float* __restrict__ b_ih, const float* __restrict__ b_hh,
             const int* __restrict__ batch, int layer) {
    __shared__ __align__(16) __nv_bfloat16 s_ahi[16 * 72];
    __shared__ __align__(16) __nv_bfloat16 s_alo[16 * 72];
    __shared__ __align__(16) __nv_bfloat16 s_hhi[16 * 72];
    __shared__ __align__(16) __nv_bfloat16 s_hlo[16 * 72];
    __shared__ __align__(16) float s_hf[16 * 66];

    int tid = threadIdx.x;
    int wid = tid >> 5, lane = tid & 31;
    int tg = lane & 3, gid = lane >> 2;
    int dbase = wid * 8;
    int d0 = dbase + tg * 2;

    // B fragments: gates 0..2 = w_ih rows, 3..5 = w_hh rows.
    unsigned Bhi[6][4][2], Blo[6][4][2];
#pragma unroll
    for (int g = 0; g < 6; g++) {
        const float* wm = (g < 3) ? w_ih : w_hh;
        const float* wr = wm + ((g % 3) * 64 + dbase + gid) * 64;
#pragma unroll
        for (int kt = 0; kt < 4; kt++) {
            int k0 = kt * 16 + tg * 2;
            split_pair(wr[k0],     wr[k0 + 1], Bhi[g][kt][0], Blo[g][kt][0]);
            split_pair(wr[k0 + 8], wr[k0 + 9], Bhi[g][kt][1], Blo[g][kt][1]);
        }
    }
    float bi0[2], bi1[2], bi2[2], bh0[2], bh1[2], bh2[2];
#pragma unroll
    for (int j = 0; j < 2; j++) {
        bi0[j] = b_ih[d0 + j];       bh0[j] = b_hh[d0 + j];
        bi1[j] = b_ih[64 + d0 + j];  bh1[j] = b_hh[64 + d0 + j];
        bi2[j] = b_ih[128 + d0 + j]; bh2[j] = b_hh[128 + d0 + j];
    }

    const float* hin = layer ? g_h : x;

    for (int chunk = blockIdx.x * 16; chunk < NN; chunk += gridDim.x * 16) {
        __syncthreads();
#pragma unroll
        for (int i = 0; i < 4; i++) {
            int idx = tid + i * 256;
            int row = idx >> 6, col = idx & 63;
            float a = g_agg[chunk * 64 + idx];
            float h = hin[chunk * 64 + idx];
            __nv_bfloat16 hh, ll;
            split1(a, hh, ll);
            s_ahi[row * 72 + col] = hh;
            s_alo[row * 72 + col] = ll;
            split1(h, hh, ll);
            s_hhi[row * 72 + col] = hh;
            s_hlo[row * 72 + col] = ll;
            s_hf[row * 66 + col] = h;
        }
        __syncthreads();

        float C[6][4];
#pragma unroll
        for (int g = 0; g < 6; g++)
#pragma unroll
            for (int q = 0; q < 4; q++) C[g][q] = 0.f;

#pragma unroll
        for (int kt = 0; kt < 4; kt++) {
            int k0 = kt * 16 + tg * 2;
            unsigned ahi[4], alo[4];
            // agg tile -> gates 0..2 (i_r, i_z, i_n)
            ahi[0] = *(const unsigned*)&s_ahi[(gid)     * 72 + k0];
            ahi[1] = *(const unsigned*)&s_ahi[(gid + 8) * 72 + k0];
            ahi[2] = *(const unsigned*)&s_ahi[(gid)     * 72 + k0 + 8];
            ahi[3] = *(const unsigned*)&s_ahi[(gid + 8) * 72 + k0 + 8];
            alo[0] = *(const unsigned*)&s_alo[(gid)     * 72 + k0];
            alo[1] = *(const unsigned*)&s_alo[(gid + 8) * 72 + k0];
            alo[2] = *(const unsigned*)&s_alo[(gid)     * 72 + k0 + 8];
            alo[3] = *(const unsigned*)&s_alo[(gid + 8) * 72 + k0 + 8];
#pragma unroll
            for (int g = 0; g < 3; g++) {
                mma16816(C[g], ahi, Bhi[g][kt]);
                mma16816(C[g], ahi, Blo[g][kt]);
                mma16816(C[g], alo, Bhi[g][kt]);
            }
            // h tile -> gates 3..5 (h_r, h_z, h_n)
            ahi[0] = *(const unsigned*)&s_hhi[(gid)     * 72 + k0];
            ahi[1] = *(const unsigned*)&s_hhi[(gid + 8) * 72 + k0];
            ahi[2] = *(const unsigned*)&s_hhi[(gid)     * 72 + k0 + 8];
            ahi[3] = *(const unsigned*)&s_hhi[(gid + 8) * 72 + k0 + 8];
            alo[0] = *(const unsigned*)&s_hlo[(gid)     * 72 + k0];
            alo[1] = *(const unsigned*)&s_hlo[(gid + 8) * 72 + k0];
            alo[2] = *(const unsigned*)&s_hlo[(gid)     * 72 + k0 + 8];
            alo[3] = *(const unsigned*)&s_hlo[(gid + 8) * 72 + k0 + 8];
#pragma unroll
            for (int g = 3; g < 6; g++) {
                mma16816(C[g], ahi, Bhi[g][kt]);
                mma16816(C[g], ahi, Blo[g][kt]);
                mma16816(C[g], alo, Bhi[g][kt]);
            }
        }

        // GRU elementwise epilogue (per-thread: 2 rows x 2 dims)
#pragma unroll
        for (int p = 0; p < 2; p++) {
            int row = gid + p * 8;
            int node = chunk + row;
            float hv[2];
#pragma unroll
            for (int j = 0; j < 2; j++) {
                int q = p * 2 + j;
                float r  = sigf(C[0][q] + bi0[j] + C[3][q] + bh0[j]);
                float z  = sigf(C[1][q] + bi1[j] + C[4][q] + bh1[j]);
                float nn = tanhfast(C[2][q] + bi2[j] + r * (C[5][q] + bh2[j]));
                float ho = s_hf[row * 66 + d0 + j];
                hv[j] = (1.f - z) * nn + z * ho;
            }
            if (layer == 0) {
                *(float2*)&g_h[node * 64 + d0] = make_float2(hv[0], hv[1]);
            } else {
                float2 rv = make_float2(fmaxf(hv[0], 0.f), fmaxf(hv[1], 0.f));
                atomicAdd((float2*)&g_pooled[batch[node] * 64 + d0], rv);
            }
        }
    }
}

// ---------------- mean pool + fc1(relu) + fc2 + log_softmax -----------------
__global__ void k_poolfc(const float* __restrict__ fc1w, const float* __restrict__ fc1b,
                         const float* __restrict__ fc2w, const float* __restrict__ fc2b,
                         float* __restrict__ out) {
    int g = threadIdx.x;
    if (g >= NG) return;
    float inv = 1.f / fmaxf((float)g_cnt[g], 1.f);
    float p[D];
#pragma unroll
    for (int k = 0; k < D; k++) p[k] = g_pooled[g * D + k] * inv;

    float y[DH];
#pragma unroll
    for (int j = 0; j < DH; j++) {
        float s = fc1b[j];
#pragma unroll
        for (int k = 0; k < D; k++) s += p[k] * fc1w[j * D + k];
        y[j] = fmaxf(s, 0.f);
    }

    float z[NC];
    float mx = -1e30f;
#pragma unroll
    for (int c = 0; c < NC; c++) {
        float s = fc2b[c];
#pragma unroll
        for (int j = 0; j < DH; j++) s += y[j] * fc2w[c * DH + j];
        z[c] = s;
        mx = fmaxf(mx, s);
    }
    float lse = 0.f;
#pragma unroll
    for (int c = 0; c < NC; c++) lse += expf(z[c] - mx);
    lse = logf(lse) + mx;
#pragma unroll
    for (int c = 0; c < NC; c++) out[g * NC + c] = z[c] - lse;
}

// ---------------- launch -----------------------------------------------------
extern "C" void kernel_launch(void* const* d_in, const int* in_sizes, int n_in,
                              void* d_out, int out_size) {
    const float* x     = (const float*)d_in[0];
    const int*   ei    = (const int*)d_in[1];
    const int*   batch = (const int*)d_in[2];
    const float* W     = (const float*)d_in[3];
    const float* w_ih  = (const float*)d_in[4];
    const float* w_hh  = (const float*)d_in[5];
    const float* b_ih  = (const float*)d_in[6];
    const float* b_hh  = (const float*)d_in[7];
    const float* fc1w  = (const float*)d_in[8];
    const float* fc1b  = (const float*)d_in[9];
    const float* fc2w  = (const float*)d_in[10];
    const float* fc2b  = (const float*)d_in[11];
    float* out = (float*)d_out;

    k_init<<<1, 256>>>(batch);
    k_count<<<(NN + 255) / 256, 256>>>(batch);

    for (int l = 0; l < 2; l++) {
        k_mgemm<<<592, 256>>>(x, W, l);
        k_scatter<<<(NE * 16) / 256, 256>>>(ei);
        k_gates<<<296, 256>>>(x, w_ih, w_hh, b_ih, b_hh, batch, l);
    }
    k_poolfc<<<1, 128>>>(fc1w, fc1b, fc2w, fc2b, out);
}